// round 4
// baseline (speedup 1.0000x reference)
#include <cuda_runtime.h>

#define PLANES 96
#define BINS   25
#define HH     512
#define WW     512
#define HWF    262144.0f
#define NBLK   1536
#define FULLM  0xFFFFFFFFu
#define W0 0.015625f
#define W1 0.09375f
#define W2 0.234375f
#define W3 0.3125f

__device__ unsigned int g_hist[2][PLANES][BINS];
__device__ unsigned int g_ticket;

// Lane owns 8 UNIQUE contiguous input cols [8l, 8l+7] of its 256-col strip
// (bytes [32l, 32l+32): the warp tiles exactly 1KB, 100% line utilization,
// zero redundant loads). Halo taps come from 5 warp shuffles in hconv.
struct Row {
    float4 q0, q1;
    float  lh_y, lh_z, lh_w;   // lane 0 only: cols -3..-1 (when strip==1)
    float  rh_x, rh_y;         // lane 31 only: cols 256,257 (when strip==0)
};

__device__ __forceinline__ void load_row(Row& R, const float* __restrict__ base,
                                         int r, int lane, int strip) {
    R.q0 = make_float4(0.f, 0.f, 0.f, 0.f);
    R.q1 = R.q0;
    R.lh_y = R.lh_z = R.lh_w = R.rh_x = R.rh_y = 0.f;
    if ((unsigned)r < (unsigned)HH) {
        const float4* p = (const float4*)(base + (size_t)r * WW);
        R.q0 = p[0];
        R.q1 = p[1];
        if (lane == 0 && strip == 1) {            // left inter-strip halo
            float4 lh = *(const float4*)(base + (size_t)r * WW - 4);
            R.lh_y = lh.y; R.lh_z = lh.z; R.lh_w = lh.w;
        }
        if (lane == 31 && strip == 0) {           // right inter-strip halo
            float2 rh = *(const float2*)(base + (size_t)r * WW + 8);
            R.rh_x = rh.x; R.rh_y = rh.y;
        }
    }
}

// Horizontal 7-tap pascal, stride 2, 4 outputs/lane. Same pairwise association
// as rounds 1-3 (rel_err 0.0). 5 shuffles supply the halo taps.
__device__ __forceinline__ void hconv(const Row& R, int lane, float h[4]) {
    float m1 = __shfl_up_sync(FULLM, R.q1.w, 1);    // col 8l-1
    float m2 = __shfl_up_sync(FULLM, R.q1.z, 1);    // col 8l-2
    float m3 = __shfl_up_sync(FULLM, R.q1.y, 1);    // col 8l-3
    float p8 = __shfl_down_sync(FULLM, R.q0.x, 1);  // col 8l+8
    float p9 = __shfl_down_sync(FULLM, R.q0.y, 1);  // col 8l+9
    if (lane == 0)  { m3 = R.lh_y; m2 = R.lh_z; m1 = R.lh_w; }
    if (lane == 31) { p8 = R.rh_x; p9 = R.rh_y; }

    h[0] = W0*(m3     + R.q0.w) + W1*(m2     + R.q0.z) + W2*(m1     + R.q0.y) + W3*R.q0.x;
    h[1] = W0*(m1     + R.q1.y) + W1*(R.q0.x + R.q1.x) + W2*(R.q0.y + R.q0.w) + W3*R.q0.z;
    h[2] = W0*(R.q0.y + R.q1.w) + W1*(R.q0.z + R.q1.z) + W2*(R.q0.w + R.q1.y) + W3*R.q1.x;
    h[3] = W0*(R.q0.w + p9)     + W1*(R.q1.x + p8)     + W2*(R.q1.y + R.q1.w) + W3*R.q1.z;
}

__global__ __launch_bounds__(128) void fused_hist_loss_kernel(
    const float* __restrict__ x, const float* __restrict__ y,
    float* __restrict__ out)
{
    __shared__ unsigned int s_cnt[BINS][128];
    __shared__ float        s_red[128];
    __shared__ unsigned int s_last;

    const int tid  = threadIdx.x;
    const int lane = tid & 31;
    const int wrp  = tid >> 5;

    const int bi      = blockIdx.x;        // 1536 = 192 planes * 4 quarters * 2 strips
    const int strip   = bi & 1;
    const int quarter = (bi >> 1) & 3;
    const int pz      = bi >> 3;           // 0..191
    const int tsel    = (pz >= PLANES) ? 1 : 0;
    const int plane   = pz - tsel * PLANES;

    const float* __restrict__ in = (tsel ? y : x) + (size_t)plane * HH * WW;
    const float* base = in + strip * 256 + 8 * lane;

    // Warp band: 16 output rows -> input rows [32*band-3, 32*band+33].
    const int band = quarter * 4 + wrp;    // 0..15
    const int rb0  = 32 * band - 3;
    unsigned int* myc = &s_cnt[0][tid];

    Row Ra, Rb;
    load_row(Ra, base, rb0,     lane, strip);
    load_row(Rb, base, rb0 + 1, lane, strip);

#pragma unroll
    for (int i = tid; i < BINS * 128; i += 128) ((unsigned int*)s_cnt)[i] = 0u;
    __syncthreads();

    // Vertical conv via 3 rolling accumulators (structure identical to round 3).
    float h[4], accA[4], accB[4], accC[4];

    hconv(Ra, lane, h);                                     // row rb0 -> B w0
#pragma unroll
    for (int j = 0; j < 4; j++) { accA[j] = 0.f; accB[j] = W0 * h[j]; }
    load_row(Ra, base, rb0 + 2, lane, strip);
    hconv(Rb, lane, h);                                     // row rb0+1 -> B w1
#pragma unroll
    for (int j = 0; j < 4; j++) accB[j] = fmaf(W1, h[j], accB[j]);
    load_row(Rb, base, rb0 + 3, lane, strip);
    hconv(Ra, lane, h);                                     // row rb0+2 -> B w2, C w0
#pragma unroll
    for (int j = 0; j < 4; j++) { accB[j] = fmaf(W2, h[j], accB[j]); accC[j] = W0 * h[j]; }
    load_row(Ra, base, rb0 + 4, lane, strip);

#pragma unroll 1
    for (int g = 0; g < 17; g++) {
        hconv(Rb, lane, h);                                 // even row rb0+3+2g
#pragma unroll
        for (int j = 0; j < 4; j++) {
            accA[j] = fmaf(W1, h[j], accA[j]);
            accB[j] = fmaf(W3, h[j], accB[j]);
            accC[j] = fmaf(W1, h[j], accC[j]);
        }
        load_row(Rb, base, g < 16 ? rb0 + 5 + 2 * g : -1, lane, strip);
        hconv(Ra, lane, h);                                 // odd row rb0+4+2g
#pragma unroll
        for (int j = 0; j < 4; j++) accA[j] = fmaf(W0, h[j], accA[j]);
        if (g > 0) {
#pragma unroll
            for (int j = 0; j < 4; j++) {
                float v = accA[j];
                if (v >= 0.0f && v <= 1.0f) {               // torch.histc(v,25,0,1)
                    int b = (int)(v * 25.0f); b = b > 24 ? 24 : b;
                    myc[b * 128] += 1u;
                }
            }
        }
#pragma unroll
        for (int j = 0; j < 4; j++) {
            accA[j] = fmaf(W2, h[j], accB[j]);
            accB[j] = fmaf(W2, h[j], accC[j]);
            accC[j] = W0 * h[j];
        }
        load_row(Ra, base, g < 16 ? rb0 + 6 + 2 * g : -1, lane, strip);
    }
    __syncthreads();

    // Block-reduce private counters -> 25 global atomics.
    for (int bin = wrp; bin < BINS; bin += 4) {
        unsigned int sum = 0;
#pragma unroll
        for (int j = 0; j < 4; j++) sum += s_cnt[bin][lane + 32 * j];
#pragma unroll
        for (int off = 16; off; off >>= 1) sum += __shfl_down_sync(FULLM, sum, off);
        if (lane == 0) atomicAdd(&g_hist[tsel][plane][bin], sum);
    }

    // Last-block finalize.
    __threadfence();
    __syncthreads();
    if (tid == 0) {
        unsigned int t = atomicAdd(&g_ticket, 1u);
        s_last = (t == NBLK - 1) ? 1u : 0u;
    }
    __syncthreads();
    if (!s_last) return;

    float cosv = 0.0f;
    if (tid < PLANES) {
        float dot = 0.0f, nx = 0.0f, ny = 0.0f;
#pragma unroll
        for (int b = 0; b < BINS; b++) {
            float xv = (float)__ldcg(&g_hist[0][tid][b]);
            float yv = (float)__ldcg(&g_hist[1][tid][b]);
            dot = fmaf(xv, yv, dot);
            nx  = fmaf(xv, xv, nx);
            ny  = fmaf(yv, yv, ny);
        }
        float nxs = fmaxf(sqrtf(nx) * (1.0f / HWF), 1e-6f);
        float nys = fmaxf(sqrtf(ny) * (1.0f / HWF), 1e-6f);
        cosv = (dot * (1.0f / (HWF * HWF))) / (nxs * nys);
    }
    s_red[tid] = cosv;
    __syncthreads();
#pragma unroll
    for (int stride = 64; stride > 0; stride >>= 1) {
        if (tid < stride) s_red[tid] += s_red[tid + stride];
        __syncthreads();
    }
    if (tid == 0) out[0] = s_red[0] * (1.0f / 96.0f);

    __syncthreads();
    for (int i = tid; i < 2 * PLANES * BINS; i += 128)
        ((unsigned int*)g_hist)[i] = 0u;
    if (tid == 0) g_ticket = 0u;
}

extern "C" void kernel_launch(void* const* d_in, const int* in_sizes, int n_in,
                              void* d_out, int out_size) {
    const float* x = (const float*)d_in[0];
    const float* y = (const float*)d_in[1];
    fused_hist_loss_kernel<<<NBLK, 128>>>(x, y, (float*)d_out);
}

// round 5
// speedup vs baseline: 1.1231x; 1.1231x over previous
#include <cuda_runtime.h>

#define PLANES 96
#define BINS   25
#define HH     512
#define WW     512
#define HWF    262144.0f
#define NBLK   1536
#define FULLM  0xFFFFFFFFu
#define W0 0.015625f
#define W1 0.09375f
#define W2 0.234375f
#define W3 0.3125f

__device__ unsigned int g_hist[2][PLANES][BINS];
__device__ unsigned int g_ticket;

// Lane owns 8 UNIQUE contiguous input cols [8l, 8l+7] (bytes [32l,32l+32)):
// warp tiles exactly 1KB per row, 100% line utilization, 4 lines/LDG wavefront.
struct Row {
    float4 q0, q1;
    float  lh_y, lh_z, lh_w;   // lane 0 only: cols -3..-1 (strip 1)
    float  rh_x, rh_y;         // lane 31 only: cols 256,257 (strip 0)
};

__device__ __forceinline__ void load_row(Row& R, const float* __restrict__ base,
                                         int r, int lane, int strip) {
    if ((unsigned)r < (unsigned)HH) {          // warp-uniform branch (r uniform)
        const float* rowp = base + (size_t)r * WW;
        const float4* p = (const float4*)rowp;
        R.q0 = p[0];
        R.q1 = p[1];
        if (lane == 0 && strip == 1) {
            float4 lh = *(const float4*)(rowp - 4);
            R.lh_y = lh.y; R.lh_z = lh.z; R.lh_w = lh.w;
        } else { R.lh_y = R.lh_z = R.lh_w = 0.f; }
        if (lane == 31 && strip == 0) {
            float2 rh = *(const float2*)(rowp + 8);
            R.rh_x = rh.x; R.rh_y = rh.y;
        } else { R.rh_x = R.rh_y = 0.f; }
    } else {
        R.q0 = make_float4(0.f, 0.f, 0.f, 0.f);
        R.q1 = R.q0;
        R.lh_y = R.lh_z = R.lh_w = R.rh_x = R.rh_y = 0.f;
    }
}

// Horizontal 7-tap pascal, stride 2, 4 outputs/lane. Association identical to
// the rel_err-0.0 kernels.
__device__ __forceinline__ void hconv(const Row& R, int lane, float h[4]) {
    float m1 = __shfl_up_sync(FULLM, R.q1.w, 1);
    float m2 = __shfl_up_sync(FULLM, R.q1.z, 1);
    float m3 = __shfl_up_sync(FULLM, R.q1.y, 1);
    float p8 = __shfl_down_sync(FULLM, R.q0.x, 1);
    float p9 = __shfl_down_sync(FULLM, R.q0.y, 1);
    if (lane == 0)  { m3 = R.lh_y; m2 = R.lh_z; m1 = R.lh_w; }
    if (lane == 31) { p8 = R.rh_x; p9 = R.rh_y; }

    h[0] = W0*(m3     + R.q0.w) + W1*(m2     + R.q0.z) + W2*(m1     + R.q0.y) + W3*R.q0.x;
    h[1] = W0*(m1     + R.q1.y) + W1*(R.q0.x + R.q1.x) + W2*(R.q0.y + R.q0.w) + W3*R.q0.z;
    h[2] = W0*(R.q0.y + R.q1.w) + W1*(R.q0.z + R.q1.z) + W2*(R.q0.w + R.q1.y) + W3*R.q1.x;
    h[3] = W0*(R.q0.w + p9)     + W1*(R.q1.x + p8)     + W2*(R.q1.y + R.q1.w) + W3*R.q1.z;
}

__global__ __launch_bounds__(128, 6) void fused_hist_loss_kernel(
    const float* __restrict__ x, const float* __restrict__ y,
    float* __restrict__ out)
{
    __shared__ unsigned int s_cnt[BINS][128];
    __shared__ float        s_red[128];
    __shared__ unsigned int s_last;

    const int tid  = threadIdx.x;
    const int lane = tid & 31;
    const int wrp  = tid >> 5;

    const int bi      = blockIdx.x;        // 1536 = 192 planes * 4 quarters * 2 strips
    const int strip   = bi & 1;
    const int quarter = (bi >> 1) & 3;
    const int pz      = bi >> 3;
    const int tsel    = (pz >= PLANES) ? 1 : 0;
    const int plane   = pz - tsel * PLANES;

    const float* __restrict__ in = (tsel ? y : x) + (size_t)plane * HH * WW;
    const float* base = in + strip * 256 + 8 * lane;

    const int band = quarter * 4 + wrp;    // 0..15, 16 output rows each
    const int rb0  = 32 * band - 3;        // input rows rb0..rb0+36
    unsigned int* myc = &s_cnt[0][tid];

    // 4-row ring buffer: every row is loaded ~2 pair-iterations (>1200 cyc of
    // SMSP issue) before consumption -> DRAM latency fully hidden.
    Row R0, R1, R2, R3;
    load_row(R0, base, rb0,     lane, strip);
    load_row(R1, base, rb0 + 1, lane, strip);
    load_row(R2, base, rb0 + 2, lane, strip);
    load_row(R3, base, rb0 + 3, lane, strip);

#pragma unroll
    for (int i = tid; i < BINS * 128; i += 128) ((unsigned int*)s_cnt)[i] = 0u;
    __syncthreads();

    float h[4], accA[4], accB[4], accC[4];

    // Prologue: consume rows 0..2, replenish slots with rows 4..6.
    hconv(R0, lane, h);
#pragma unroll
    for (int j = 0; j < 4; j++) { accA[j] = 0.f; accB[j] = W0 * h[j]; }
    load_row(R0, base, rb0 + 4, lane, strip);
    hconv(R1, lane, h);
#pragma unroll
    for (int j = 0; j < 4; j++) accB[j] = fmaf(W1, h[j], accB[j]);
    load_row(R1, base, rb0 + 5, lane, strip);
    hconv(R2, lane, h);
#pragma unroll
    for (int j = 0; j < 4; j++) { accB[j] = fmaf(W2, h[j], accB[j]); accC[j] = W0 * h[j]; }
    load_row(R2, base, rb0 + 6, lane, strip);

    // Pair g consumes rows (3+2g, 4+2g) and loads rows (7+2g, 8+2g) into the
    // same slots. Odd rows alternate slots R3/R1, even rows R0/R2.
#define PAIR(RO, RE, g, DO_LOAD)                                              \
    do {                                                                       \
        hconv(RO, lane, h);                                                    \
        _Pragma("unroll")                                                      \
        for (int j = 0; j < 4; j++) {                                          \
            accA[j] = fmaf(W1, h[j], accA[j]);                                 \
            accB[j] = fmaf(W3, h[j], accB[j]);                                 \
            accC[j] = fmaf(W1, h[j], accC[j]);                                 \
        }                                                                      \
        if (DO_LOAD) load_row(RO, base, rb0 + 7 + 2 * (g), lane, strip);       \
        hconv(RE, lane, h);                                                    \
        _Pragma("unroll")                                                      \
        for (int j = 0; j < 4; j++) accA[j] = fmaf(W0, h[j], accA[j]);         \
        if ((g) > 0) {                                                         \
            _Pragma("unroll")                                                  \
            for (int j = 0; j < 4; j++) {                                      \
                float v = accA[j];                                             \
                if (v >= 0.0f && v <= 1.0f) {   /* torch.histc(v,25,0,1) */    \
                    int b = (int)(v * 25.0f); b = b > 24 ? 24 : b;             \
                    myc[b * 128] += 1u;                                        \
                }                                                              \
            }                                                                  \
        }                                                                      \
        _Pragma("unroll")                                                      \
        for (int j = 0; j < 4; j++) {                                          \
            accA[j] = fmaf(W2, h[j], accB[j]);                                 \
            accB[j] = fmaf(W2, h[j], accC[j]);                                 \
            accC[j] = W0 * h[j];                                               \
        }                                                                      \
        if (DO_LOAD) load_row(RE, base, rb0 + 8 + 2 * (g), lane, strip);       \
    } while (0)

#pragma unroll 1
    for (int gg = 0; gg < 7; gg++) {       // g = 0..13, loads valid (rows <= 36)
        int g = 2 * gg;
        PAIR(R3, R0, g, 1);
        PAIR(R1, R2, g + 1, 1);
    }
    PAIR(R3, R0, 14, 1);                   // loads rows 35,36 (last valid)
    PAIR(R1, R2, 15, 0);
    PAIR(R3, R0, 16, 0);                   // retires output row 15
#undef PAIR

    __syncthreads();

    // Block-reduce private counters -> 25 global atomics.
    for (int bin = wrp; bin < BINS; bin += 4) {
        unsigned int sum = 0;
#pragma unroll
        for (int j = 0; j < 4; j++) sum += s_cnt[bin][lane + 32 * j];
#pragma unroll
        for (int off = 16; off; off >>= 1) sum += __shfl_down_sync(FULLM, sum, off);
        if (lane == 0) atomicAdd(&g_hist[tsel][plane][bin], sum);
    }

    // Last-block finalize.
    __threadfence();
    __syncthreads();
    if (tid == 0) {
        unsigned int t = atomicAdd(&g_ticket, 1u);
        s_last = (t == NBLK - 1) ? 1u : 0u;
    }
    __syncthreads();
    if (!s_last) return;

    float cosv = 0.0f;
    if (tid < PLANES) {
        float dot = 0.0f, nx = 0.0f, ny = 0.0f;
#pragma unroll
        for (int b = 0; b < BINS; b++) {
            float xv = (float)__ldcg(&g_hist[0][tid][b]);
            float yv = (float)__ldcg(&g_hist[1][tid][b]);
            dot = fmaf(xv, yv, dot);
            nx  = fmaf(xv, xv, nx);
            ny  = fmaf(yv, yv, ny);
        }
        float nxs = fmaxf(sqrtf(nx) * (1.0f / HWF), 1e-6f);
        float nys = fmaxf(sqrtf(ny) * (1.0f / HWF), 1e-6f);
        cosv = (dot * (1.0f / (HWF * HWF))) / (nxs * nys);
    }
    s_red[tid] = cosv;
    __syncthreads();
#pragma unroll
    for (int stride = 64; stride > 0; stride >>= 1) {
        if (tid < stride) s_red[tid] += s_red[tid + stride];
        __syncthreads();
    }
    if (tid == 0) out[0] = s_red[0] * (1.0f / 96.0f);

    __syncthreads();
    for (int i = tid; i < 2 * PLANES * BINS; i += 128)
        ((unsigned int*)g_hist)[i] = 0u;
    if (tid == 0) g_ticket = 0u;
}

extern "C" void kernel_launch(void* const* d_in, const int* in_sizes, int n_in,
                              void* d_out, int out_size) {
    const float* x = (const float*)d_in[0];
    const float* y = (const float*)d_in[1];
    fused_hist_loss_kernel<<<NBLK, 128>>>(x, y, (float*)d_out);
}

// round 6
// speedup vs baseline: 1.2434x; 1.1072x over previous
#include <cuda_runtime.h>

#define PLANES 96
#define BINS   25
#define HH     512
#define WW     512
#define HWF    262144.0f
#define NBLK   768
#define FULLM  0xFFFFFFFFu
#define W0 0.015625f
#define W1 0.09375f
#define W2 0.234375f
#define W3 0.3125f

__device__ unsigned int g_hist[2][PLANES][BINS];
__device__ unsigned int g_ticket;

// Lane owns 8 UNIQUE contiguous input cols [8l, 8l+7] (bytes [32l,32l+32)):
// warp tiles exactly 1KB per row, 100% line utilization.
struct Row {
    float4 q0, q1;
    float  lh_y, lh_z, lh_w;   // lane 0 only: cols -3..-1 (strip 1)
    float  rh_x, rh_y;         // lane 31 only: cols 256,257 (strip 0)
};

__device__ __forceinline__ void load_row(Row& R, const float* __restrict__ base,
                                         int r, int lane, int strip) {
    if ((unsigned)r < (unsigned)HH) {          // warp-uniform branch (r uniform)
        const float* rowp = base + (size_t)r * WW;
        const float4* p = (const float4*)rowp;
        R.q0 = p[0];
        R.q1 = p[1];
        if (lane == 0 && strip == 1) {
            float4 lh = *(const float4*)(rowp - 4);
            R.lh_y = lh.y; R.lh_z = lh.z; R.lh_w = lh.w;
        } else { R.lh_y = R.lh_z = R.lh_w = 0.f; }
        if (lane == 31 && strip == 0) {
            float2 rh = *(const float2*)(rowp + 8);
            R.rh_x = rh.x; R.rh_y = rh.y;
        } else { R.rh_x = R.rh_y = 0.f; }
    } else {
        R.q0 = make_float4(0.f, 0.f, 0.f, 0.f);
        R.q1 = R.q0;
        R.lh_y = R.lh_z = R.lh_w = R.rh_x = R.rh_y = 0.f;
    }
}

// Horizontal 7-tap pascal, stride 2, 4 outputs/lane. Association identical to
// the rel_err-0.0 kernels.
__device__ __forceinline__ void hconv(const Row& R, int lane, float h[4]) {
    float m1 = __shfl_up_sync(FULLM, R.q1.w, 1);
    float m2 = __shfl_up_sync(FULLM, R.q1.z, 1);
    float m3 = __shfl_up_sync(FULLM, R.q1.y, 1);
    float p8 = __shfl_down_sync(FULLM, R.q0.x, 1);
    float p9 = __shfl_down_sync(FULLM, R.q0.y, 1);
    if (lane == 0)  { m3 = R.lh_y; m2 = R.lh_z; m1 = R.lh_w; }
    if (lane == 31) { p8 = R.rh_x; p9 = R.rh_y; }

    h[0] = W0*(m3     + R.q0.w) + W1*(m2     + R.q0.z) + W2*(m1     + R.q0.y) + W3*R.q0.x;
    h[1] = W0*(m1     + R.q1.y) + W1*(R.q0.x + R.q1.x) + W2*(R.q0.y + R.q0.w) + W3*R.q0.z;
    h[2] = W0*(R.q0.y + R.q1.w) + W1*(R.q0.z + R.q1.z) + W2*(R.q0.w + R.q1.y) + W3*R.q1.x;
    h[3] = W0*(R.q0.w + p9)     + W1*(R.q1.x + p8)     + W2*(R.q1.y + R.q1.w) + W3*R.q1.z;
}

__global__ __launch_bounds__(128, 6) void fused_hist_loss_kernel(
    const float* __restrict__ x, const float* __restrict__ y,
    float* __restrict__ out)
{
    __shared__ unsigned int s_cnt[BINS][128];
    __shared__ float        s_red[128];
    __shared__ unsigned int s_last;

    const int tid  = threadIdx.x;
    const int lane = tid & 31;
    const int wrp  = tid >> 5;

    const int bi    = blockIdx.x;          // 768 = 192 planes * 2 block-bands * 2 strips
    const int strip = bi & 1;
    const int bb    = (bi >> 1) & 1;
    const int pz    = bi >> 2;             // 0..191
    const int tsel  = (pz >= PLANES) ? 1 : 0;
    const int plane = pz - tsel * PLANES;

    const float* __restrict__ in = (tsel ? y : x) + (size_t)plane * HH * WW;
    const float* base = in + strip * 256 + 8 * lane;

    const int band = bb * 4 + wrp;         // 0..7, 32 output rows each
    const int rb0  = 64 * band - 3;        // input rows rb0..rb0+68 (69 rows)
    unsigned int* myc = &s_cnt[0][tid];

    // 4-row ring buffer: each row loaded 2 pair-iterations before consumption.
    Row R0, R1, R2, R3;
    load_row(R0, base, rb0,     lane, strip);
    load_row(R1, base, rb0 + 1, lane, strip);
    load_row(R2, base, rb0 + 2, lane, strip);
    load_row(R3, base, rb0 + 3, lane, strip);

#pragma unroll
    for (int i = tid; i < BINS * 128; i += 128) ((unsigned int*)s_cnt)[i] = 0u;
    __syncthreads();

    float h[4], accA[4], accB[4], accC[4];

    // Prologue: consume rows 0..2, replenish slots with rows 4..6.
    hconv(R0, lane, h);
#pragma unroll
    for (int j = 0; j < 4; j++) { accA[j] = 0.f; accB[j] = W0 * h[j]; }
    load_row(R0, base, rb0 + 4, lane, strip);
    hconv(R1, lane, h);
#pragma unroll
    for (int j = 0; j < 4; j++) accB[j] = fmaf(W1, h[j], accB[j]);
    load_row(R1, base, rb0 + 5, lane, strip);
    hconv(R2, lane, h);
#pragma unroll
    for (int j = 0; j < 4; j++) { accB[j] = fmaf(W2, h[j], accB[j]); accC[j] = W0 * h[j]; }
    load_row(R2, base, rb0 + 6, lane, strip);

    // Pair g consumes rows (3+2g, 4+2g), loads rows (7+2g, 8+2g) into the same
    // slots. Odd rows alternate slots R3/R1, even rows R0/R2.
#define PAIR(RO, RE, g, DO_LOAD)                                              \
    do {                                                                       \
        hconv(RO, lane, h);                                                    \
        _Pragma("unroll")                                                      \
        for (int j = 0; j < 4; j++) {                                          \
            accA[j] = fmaf(W1, h[j], accA[j]);                                 \
            accB[j] = fmaf(W3, h[j], accB[j]);                                 \
            accC[j] = fmaf(W1, h[j], accC[j]);                                 \
        }                                                                      \
        if (DO_LOAD) load_row(RO, base, rb0 + 7 + 2 * (g), lane, strip);       \
        hconv(RE, lane, h);                                                    \
        _Pragma("unroll")                                                      \
        for (int j = 0; j < 4; j++) accA[j] = fmaf(W0, h[j], accA[j]);         \
        if ((g) > 0) {                                                         \
            _Pragma("unroll")                                                  \
            for (int j = 0; j < 4; j++) {                                      \
                float v = accA[j];                                             \
                if (v >= 0.0f && v <= 1.0f) {   /* torch.histc(v,25,0,1) */    \
                    int b = (int)(v * 25.0f); b = b > 24 ? 24 : b;             \
                    myc[b * 128] += 1u;                                        \
                }                                                              \
            }                                                                  \
        }                                                                      \
        _Pragma("unroll")                                                      \
        for (int j = 0; j < 4; j++) {                                          \
            accA[j] = fmaf(W2, h[j], accB[j]);                                 \
            accB[j] = fmaf(W2, h[j], accC[j]);                                 \
            accC[j] = W0 * h[j];                                               \
        }                                                                      \
        if (DO_LOAD) load_row(RE, base, rb0 + 8 + 2 * (g), lane, strip);       \
    } while (0)

#pragma unroll 1
    for (int gg = 0; gg < 15; gg++) {      // g = 0..29, loads valid (rows <= 68)
        int g = 2 * gg;
        PAIR(R3, R0, g, 1);
        PAIR(R1, R2, g + 1, 1);
    }
    PAIR(R3, R0, 30, 1);                   // loads rows 67,68 (last valid)
    PAIR(R1, R2, 31, 0);
    PAIR(R3, R0, 32, 0);                   // retires output row 31
#undef PAIR

    __syncthreads();

    // Block-reduce private counters -> 25 global atomics.
    for (int bin = wrp; bin < BINS; bin += 4) {
        unsigned int sum = 0;
#pragma unroll
        for (int j = 0; j < 4; j++) sum += s_cnt[bin][lane + 32 * j];
#pragma unroll
        for (int off = 16; off; off >>= 1) sum += __shfl_down_sync(FULLM, sum, off);
        if (lane == 0) atomicAdd(&g_hist[tsel][plane][bin], sum);
    }

    // Last-block finalize.
    __threadfence();
    __syncthreads();
    if (tid == 0) {
        unsigned int t = atomicAdd(&g_ticket, 1u);
        s_last = (t == NBLK - 1) ? 1u : 0u;
    }
    __syncthreads();
    if (!s_last) return;

    float cosv = 0.0f;
    if (tid < PLANES) {
        float dot = 0.0f, nx = 0.0f, ny = 0.0f;
#pragma unroll
        for (int b = 0; b < BINS; b++) {
            float xv = (float)__ldcg(&g_hist[0][tid][b]);
            float yv = (float)__ldcg(&g_hist[1][tid][b]);
            dot = fmaf(xv, yv, dot);
            nx  = fmaf(xv, xv, nx);
            ny  = fmaf(yv, yv, ny);
        }
        float nxs = fmaxf(sqrtf(nx) * (1.0f / HWF), 1e-6f);
        float nys = fmaxf(sqrtf(ny) * (1.0f / HWF), 1e-6f);
        cosv = (dot * (1.0f / (HWF * HWF))) / (nxs * nys);
    }
    s_red[tid] = cosv;
    __syncthreads();
#pragma unroll
    for (int stride = 64; stride > 0; stride >>= 1) {
        if (tid < stride) s_red[tid] += s_red[tid + stride];
        __syncthreads();
    }
    if (tid == 0) out[0] = s_red[0] * (1.0f / 96.0f);

    __syncthreads();
    for (int i = tid; i < 2 * PLANES * BINS; i += 128)
        ((unsigned int*)g_hist)[i] = 0u;
    if (tid == 0) g_ticket = 0u;
}

extern "C" void kernel_launch(void* const* d_in, const int* in_sizes, int n_in,
                              void* d_out, int out_size) {
    const float* x = (const float*)d_in[0];
    const float* y = (const float*)d_in[1];
    fused_hist_loss_kernel<<<NBLK, 128>>>(x, y, (float*)d_out);
}